// round 5
// baseline (speedup 1.0000x reference)
#include <cuda_runtime.h>
#include <cstdint>

#define N_ROWS 50000
#define D_DIM  512
#define TILE_M 96
#define TILE_N 128
#define KC     32                   // K floats per pipeline stage
#define KSTAGES (D_DIM / KC)        // 16
#define NTHREADS 384                // 12 warps: 3 (m) x 4 (n), each 32x32

#define PITCH 144                   // bytes per SMEM row (128 data + 16 pad)
#define ROW_AI 0
#define ROW_AP 96
#define ROW_BI 192
#define ROW_BP 320
#define ROW_BS 448
#define STAGE_ROWS 576
#define STAGE_BYTES (STAGE_ROWS * PITCH)        // 82944
#define SMEM_TOTAL (2 * STAGE_BYTES)            // 165888

__device__ double g_si, g_sp, g_ss;

// ---------------- helpers ----------------
__device__ __forceinline__ uint32_t smem_u32(const void* p) {
    uint32_t a;
    asm("{ .reg .u64 t; cvta.to.shared.u64 t, %1; cvt.u32.u64 %0, t; }" : "=r"(a) : "l"(p));
    return a;
}
__device__ __forceinline__ float fast_tanh(float x) {
    float y;
    asm("tanh.approx.f32 %0, %1;" : "=f"(y) : "f"(x));
    return y;
}
__device__ __forceinline__ void cp_async16(uint32_t dst, const void* src, int nbytes) {
    asm volatile("cp.async.cg.shared.global [%0], [%1], 16, %2;"
                 :: "r"(dst), "l"(src), "r"(nbytes) : "memory");
}
__device__ __forceinline__ void ldsm4(uint32_t (&r)[4], uint32_t addr) {
    asm volatile("ldmatrix.sync.aligned.m8n8.x4.shared.b16 {%0,%1,%2,%3}, [%4];"
                 : "=r"(r[0]), "=r"(r[1]), "=r"(r[2]), "=r"(r[3]) : "r"(addr));
}
__device__ __forceinline__ uint32_t f2tf(float f) {
    uint32_t y;
    asm("cvt.rna.tf32.f32 %0, %1;" : "=r"(y) : "f"(f));
    return y;
}
__device__ __forceinline__ void mma8(float (&d)[4], const uint32_t (&a)[4],
                                     uint32_t b0, uint32_t b1) {
    asm volatile("mma.sync.aligned.m16n8k8.row.col.f32.tf32.tf32.f32 "
                 "{%0,%1,%2,%3},{%4,%5,%6,%7},{%8,%9},{%0,%1,%2,%3};"
                 : "+f"(d[0]), "+f"(d[1]), "+f"(d[2]), "+f"(d[3])
                 : "r"(a[0]), "r"(a[1]), "r"(a[2]), "r"(a[3]), "r"(b0), "r"(b1));
}

// Fill one pipeline stage: 576 rows x 128B, 16B chunks, pitch-144 layout.
__device__ __forceinline__ void fill_stage(
    uint32_t smem_base, int s, int k, int tid,
    const float* gAi, const float* gAp,
    const float* gBi, const float* gBp, const float* gBs,
    int rows_valid)
{
    const int koff = k * KC;
    const uint32_t buf = smem_base + (uint32_t)s * STAGE_BYTES;
#pragma unroll
    for (int i = 0; i < 12; i++) {
        int idx = i * NTHREADS + tid;
        int r = idx >> 3;
        int c = idx & 7;
        uint32_t dst = buf + (uint32_t)r * PITCH + (uint32_t)c * 16;
        const float* src;
        int nb = 16;
        if (r < 96) {
            int rr = (r < rows_valid) ? r : 0;
            if (r >= rows_valid) nb = 0;
            src = gAi + (size_t)rr * D_DIM + koff + c * 4;
        } else if (r < 192) {
            int rr = r - 96;
            if (rr >= rows_valid) { rr = 0; nb = 0; }
            src = gAp + (size_t)rr * D_DIM + koff + c * 4;
        } else if (r < 320) {
            src = gBi + (size_t)(r - 192) * D_DIM + koff + c * 4;
        } else if (r < 448) {
            src = gBp + (size_t)(r - 320) * D_DIM + koff + c * 4;
        } else {
            src = gBs + (size_t)(r - 448) * D_DIM + koff + c * 4;
        }
        cp_async16(dst, src, nb);
    }
    asm volatile("cp.async.commit_group;" ::: "memory");
}

__global__ void __launch_bounds__(NTHREADS, 1)
fused_mm(const float* __restrict__ img, const float* __restrict__ ph,
         const float* __restrict__ Ws, const float* __restrict__ bs,
         const float* __restrict__ Wi, const float* __restrict__ bi,
         const float* __restrict__ Wp, const float* __restrict__ bp,
         float* __restrict__ out)
{
    extern __shared__ char smem[];
    __shared__ float shb[3][TILE_N];
    __shared__ float red[12][3];
    const uint32_t smem_base = smem_u32(smem);
    const int tid = threadIdx.x;
    const int wid = tid >> 5;
    const int lane = tid & 31;
    const int warp_m = wid % 3;        // 0..2 -> 32-row slab
    const int warp_n = wid / 3;        // 0..3 -> 32-col slab
    const int g = lane >> 2;           // groupID
    const int tig = lane & 3;          // thread in group
    const int row0 = blockIdx.y * TILE_M;
    const int col0 = blockIdx.x * TILE_N;
    const int rows_valid = (N_ROWS - row0 < TILE_M) ? (N_ROWS - row0) : TILE_M;

    for (int i = tid; i < TILE_N; i += NTHREADS) {
        shb[0][i] = bi[col0 + i];
        shb[1][i] = bp[col0 + i];
        shb[2][i] = bs[col0 + i];
    }

    const float* gAi = img + (size_t)row0 * D_DIM;
    const float* gAp = ph  + (size_t)row0 * D_DIM;
    const float* gBi = Wi  + (size_t)col0 * D_DIM;
    const float* gBp = Wp  + (size_t)col0 * D_DIM;
    const float* gBs = Ws  + (size_t)col0 * D_DIM;

    // lane-constant ldmatrix address components
    // A atoms: atom = lane>>3; row += (atom&1)*8 + (lane&7); colbyte += (atom>>1)*16
    const uint32_t laneRowA = (((lane >> 3) & 1) * 8 + (lane & 7));
    const uint32_t laneColA = (lane >> 4) * 16;
    // B atoms: row += (atom>>1)*8 + (lane&7); colbyte += (atom&1)*16
    const uint32_t laneRowB = ((lane >> 4) * 8 + (lane & 7));
    const uint32_t laneColB = ((lane >> 3) & 1) * 16;

    float acc_i[2][4][4], acc_p[2][4][4], acc_s[2][4][4];
#pragma unroll
    for (int mt = 0; mt < 2; mt++)
#pragma unroll
        for (int nt = 0; nt < 4; nt++)
#pragma unroll
            for (int j = 0; j < 4; j++) {
                acc_i[mt][nt][j] = 0.f;
                acc_p[mt][nt][j] = 0.f;
                acc_s[mt][nt][j] = 0.f;
            }

    fill_stage(smem_base, 0, 0, tid, gAi, gAp, gBi, gBp, gBs, rows_valid);
    fill_stage(smem_base, 1, 1, tid, gAi, gAp, gBi, gBp, gBs, rows_valid);

    for (int k = 0; k < KSTAGES; k++) {
        const int s = k & 1;
        if (k < KSTAGES - 1) asm volatile("cp.async.wait_group 1;" ::: "memory");
        else                 asm volatile("cp.async.wait_group 0;" ::: "memory");
        __syncthreads();

        const uint32_t buf = smem_base + (uint32_t)s * STAGE_BYTES;
        const uint32_t aBase0 = buf + (ROW_AI + warp_m * 32 + laneRowA) * PITCH + laneColA;
        const uint32_t aBase1 = buf + (ROW_AP + warp_m * 32 + laneRowA) * PITCH + laneColA;
        const uint32_t bBaseI = buf + (ROW_BI + warp_n * 32 + laneRowB) * PITCH + laneColB;
        const uint32_t bBaseP = buf + (ROW_BP + warp_n * 32 + laneRowB) * PITCH + laneColB;
        const uint32_t bBaseS = buf + (ROW_BS + warp_n * 32 + laneRowB) * PITCH + laneColB;

#pragma unroll
        for (int kk = 0; kk < 4; kk++) {
            const uint32_t kb = kk * 32;
            uint32_t rawAi[2][4], rawAp[2][4];
            ldsm4(rawAi[0], aBase0 + kb);
            ldsm4(rawAi[1], aBase0 + 16 * PITCH + kb);
            ldsm4(rawAp[0], aBase1 + kb);
            ldsm4(rawAp[1], aBase1 + 16 * PITCH + kb);

            uint32_t ai[2][4], ap[2][4], as[2][4];
#pragma unroll
            for (int mt = 0; mt < 2; mt++)
#pragma unroll
                for (int j = 0; j < 4; j++) {
                    float fi = __uint_as_float(rawAi[mt][j]);
                    float fp = __uint_as_float(rawAp[mt][j]);
                    ai[mt][j] = f2tf(fi);
                    ap[mt][j] = f2tf(fp);
                    as[mt][j] = f2tf(fi + fp);   // x0.5 folded into epilogue
                }

            uint32_t bI[2][4], bP[2][4], bS[2][4];
            ldsm4(bI[0], bBaseI + kb);
            ldsm4(bI[1], bBaseI + 16 * PITCH + kb);
            ldsm4(bP[0], bBaseP + kb);
            ldsm4(bP[1], bBaseP + 16 * PITCH + kb);
            ldsm4(bS[0], bBaseS + kb);
            ldsm4(bS[1], bBaseS + 16 * PITCH + kb);
#pragma unroll
            for (int q = 0; q < 2; q++)
#pragma unroll
                for (int j = 0; j < 4; j++) {
                    bI[q][j] = f2tf(__uint_as_float(bI[q][j]));
                    bP[q][j] = f2tf(__uint_as_float(bP[q][j]));
                    bS[q][j] = f2tf(__uint_as_float(bS[q][j]));
                }

#pragma unroll
            for (int mt = 0; mt < 2; mt++)
#pragma unroll
                for (int nt = 0; nt < 4; nt++) {
                    const int q = nt >> 1, o = (nt & 1) * 2;
                    mma8(acc_i[mt][nt], ai[mt], bI[q][o], bI[q][o + 1]);
                    mma8(acc_p[mt][nt], ap[mt], bP[q][o], bP[q][o + 1]);
                    mma8(acc_s[mt][nt], as[mt], bS[q][o], bS[q][o + 1]);
                }
        }
        __syncthreads();
        if (k + 2 < KSTAGES)
            fill_stage(smem_base, s, k + 2, tid, gAi, gAp, gBi, gBp, gBs, rows_valid);
    }

    // ---------------- epilogue ----------------
    float si = 0.f, sp = 0.f, ss = 0.f;
#pragma unroll
    for (int mt = 0; mt < 2; mt++) {
#pragma unroll
        for (int h = 0; h < 2; h++) {
            const int rloc = warp_m * 32 + mt * 16 + h * 8 + g;
            if (rloc < rows_valid) {
                const size_t rbase = (size_t)(row0 + rloc) * D_DIM;
#pragma unroll
                for (int nt = 0; nt < 4; nt++) {
                    const int lc = warp_n * 32 + nt * 8 + tig * 2;
                    const float2 vi = *(const float2*)(img + rbase + col0 + lc);
                    const float2 vp = *(const float2*)(ph  + rbase + col0 + lc);
                    const int j0 = h * 2;
                    float ia0 = fast_tanh(acc_i[mt][nt][j0]     + shb[0][lc]);
                    float ia1 = fast_tanh(acc_i[mt][nt][j0 + 1] + shb[0][lc + 1]);
                    float pa0 = fast_tanh(acc_p[mt][nt][j0]     + shb[1][lc]);
                    float pa1 = fast_tanh(acc_p[mt][nt][j0 + 1] + shb[1][lc + 1]);
                    float sa0 = fast_tanh(0.5f * acc_s[mt][nt][j0]     + shb[2][lc]);
                    float sa1 = fast_tanh(0.5f * acc_s[mt][nt][j0 + 1] + shb[2][lc + 1]);
                    float2 vo;
                    vo.x = sa0 * 0.5f * (vi.x + vp.x) + ia0 * vi.x + pa0 * vp.x;
                    vo.y = sa1 * 0.5f * (vi.y + vp.y) + ia1 * vi.y + pa1 * vp.y;
                    *(float2*)(out + rbase + col0 + lc) = vo;
                    si += ia0 * ia0 + ia1 * ia1;
                    sp += pa0 * pa0 + pa1 * pa1;
                    ss += sa0 * sa0 + sa1 * sa1;
                }
            }
        }
    }

#pragma unroll
    for (int o = 16; o; o >>= 1) {
        si += __shfl_xor_sync(0xffffffffu, si, o);
        sp += __shfl_xor_sync(0xffffffffu, sp, o);
        ss += __shfl_xor_sync(0xffffffffu, ss, o);
    }
    if (lane == 0) { red[wid][0] = si; red[wid][1] = sp; red[wid][2] = ss; }
    __syncthreads();
    if (tid == 0) {
        float a = 0.f, b = 0.f, c = 0.f;
#pragma unroll
        for (int w = 0; w < 12; w++) { a += red[w][0]; b += red[w][1]; c += red[w][2]; }
        atomicAdd(&g_si, (double)a);
        atomicAdd(&g_sp, (double)b);
        atomicAdd(&g_ss, (double)c);
    }
}

__global__ void zero_acc() { g_si = 0.0; g_sp = 0.0; g_ss = 0.0; }

__global__ void finalize(float* __restrict__ out) {
    const double ss = g_ss;
    const float a = (float)(g_si / ss);
    const float b = (float)(g_sp / ss);
    const float m = fmaxf(a, b);
    const float ea = expf(a - m), eb = expf(b - m);
    const float inv = 1.f / (ea + eb);
    out[(size_t)N_ROWS * D_DIM + 0] = ea * inv;
    out[(size_t)N_ROWS * D_DIM + 1] = eb * inv;
}

extern "C" void kernel_launch(void* const* d_in, const int* in_sizes, int n_in,
                              void* d_out, int out_size) {
    const float* img = (const float*)d_in[0];
    const float* ph  = (const float*)d_in[1];
    const float* Ws  = (const float*)d_in[2];
    const float* bs  = (const float*)d_in[3];
    const float* Wi  = (const float*)d_in[4];
    const float* bi  = (const float*)d_in[5];
    const float* Wp  = (const float*)d_in[6];
    const float* bp  = (const float*)d_in[7];
    float* out = (float*)d_out;

    static bool attr_set = false;
    if (!attr_set) {
        cudaFuncSetAttribute(fused_mm, cudaFuncAttributeMaxDynamicSharedMemorySize, SMEM_TOTAL);
        attr_set = true;
    }

    zero_acc<<<1, 1>>>();
    dim3 grid(D_DIM / TILE_N, (N_ROWS + TILE_M - 1) / TILE_M);
    fused_mm<<<grid, NTHREADS, SMEM_TOTAL>>>(img, ph, Ws, bs, Wi, bi, Wp, bp, out);
    finalize<<<1, 1>>>(out);
}